// round 11
// baseline (speedup 1.0000x reference)
#include <cuda_runtime.h>
#include <cuda_bf16.h>

#define N_NODES  100000
#define N_EDGES  1600000
#define N_FEAT   32
#define HIDDEN   128
#define N_GRAPHS 256

#define SCAN_T   1024
#define SCAN_NB  98          // ceil(100000/1024)

#define UBM 128              // update kernel M-tile (nodes per block)
#define NPAD (N_NODES + UBM) // zero-padded rows for tail block

// ---------------- scratch (static device globals; no allocation) ----------------
// NOTE: hh/hl/ah/al use a PERMUTED column layout: within each 16-col chunk,
// col k sits at perm16(k) = ((k&7)>>1)*4 + (k&1) + ((k>>3)<<1), so that the
// mma a-fragment pairs (k,k+1) and (k+8,k+9) are adjacent (one LDG.64).
__device__ float         g_h [NPAD * HIDDEN];   // fp32 h, natural layout (aggregate gathers this)
__device__ __nv_bfloat16 g_hh[NPAD * HIDDEN];   // h hi (bf16, permuted)
__device__ __nv_bfloat16 g_hl[NPAD * HIDDEN];   // h lo (bf16, permuted)
__device__ __nv_bfloat16 g_ah[NPAD * HIDDEN];   // agg hi (permuted)
__device__ __nv_bfloat16 g_al[NPAD * HIDDEN];   // agg lo (permuted)
__device__ uint4 g_wfrag[16 * 16 * 32];         // [cc][j][lane] = {bh0,bh1,bl0,bl1}, 128KB
__device__ int   g_degi[N_NODES];
__device__ int   g_rowptr[N_NODES + 1];
__device__ int   g_cursor[N_NODES];
__device__ int   g_ssrc[N_EDGES];               // 6.4 MB
__device__ int   g_bsum[SCAN_NB];
__device__ float g_cnt[N_GRAPHS];
__device__ float g_pool[N_GRAPHS * HIDDEN];

// ---------------- helpers ----------------
__device__ __forceinline__ int perm16(int k) {
    return ((k & 7) >> 1) * 4 + (k & 1) + ((k >> 3) << 1);
}

__device__ __forceinline__ void red_add_v4(float* addr, float4 v) {
    asm volatile("red.global.add.v4.f32 [%0], {%1, %2, %3, %4};"
                 :: "l"(addr), "f"(v.x), "f"(v.y), "f"(v.z), "f"(v.w)
                 : "memory");
}

__device__ __forceinline__ unsigned pack_bf2(__nv_bfloat16 a, __nv_bfloat16 b) {
    __nv_bfloat162 t;
    t.x = a; t.y = b;
    return *reinterpret_cast<unsigned*>(&t);
}

__device__ __forceinline__ void split_bf(float v, __nv_bfloat16& hi, __nv_bfloat16& lo) {
    hi = __float2bfloat16(v);
    lo = __float2bfloat16(v - __bfloat162float(hi));
}

__device__ __forceinline__ void mma16816(float* d, const unsigned* a, unsigned b0, unsigned b1) {
    asm volatile(
        "mma.sync.aligned.m16n8k16.row.col.f32.bf16.bf16.f32 "
        "{%0,%1,%2,%3}, {%4,%5,%6,%7}, {%8,%9}, {%0,%1,%2,%3};\n"
        : "+f"(d[0]), "+f"(d[1]), "+f"(d[2]), "+f"(d[3])
        : "r"(a[0]), "r"(a[1]), "r"(a[2]), "r"(a[3]), "r"(b0), "r"(b1));
}

// write a lane's 4 contiguous logical cols (4q..4q+3 within chunk) into permuted layout
__device__ __forceinline__ void store_perm4(__nv_bfloat16* basep, long long rowofs, int lane,
                                            __nv_bfloat16 v0, __nv_bfloat16 v1,
                                            __nv_bfloat16 v2, __nv_bfloat16 v3) {
    int chunkbase = (lane >> 2) * 16;
    int q = lane & 3;
    int posA = perm16(4 * q);       // pair (4q, 4q+1)
    int posB = perm16(4 * q + 2);   // pair (4q+2, 4q+3)
    *(unsigned*)(basep + rowofs + chunkbase + posA) = pack_bf2(v0, v1);
    *(unsigned*)(basep + rowofs + chunkbase + posB) = pack_bf2(v2, v3);
}

// ---------------- zero: degi, cnt, pool ----------------
__global__ void zero_kernel(int* __restrict__ degi, float* __restrict__ cnt,
                            float* __restrict__ pool)
{
    int i = blockIdx.x * blockDim.x + threadIdx.x;
    int stride = gridDim.x * blockDim.x;
    for (int j = i; j < N_NODES; j += stride) degi[j] = 0;
    for (int j = i; j < N_GRAPHS * HIDDEN; j += stride) pool[j] = 0.f;
    if (i < N_GRAPHS) cnt[i] = 0.f;
}

// ---------------- weight pre-split into uint4 b-fragment records ----------------
// idx = (cc*16 + j)*32 + lane ; lane=(gq<<2)|tg ; n = j*8+gq ; kb = cc*16+2tg
// record = { pack(W[kb],W[kb+1]) , pack(W[kb+8],W[kb+9]) , same-lo , same-lo }
__global__ void wsplit_kernel(const float* __restrict__ Wl, const float* __restrict__ Wr,
                              uint4* __restrict__ wfrag)
{
    int idx = blockIdx.x * 256 + threadIdx.x;      // 0..8191
    int lane = idx & 31;
    int j    = (idx >> 5) & 15;
    int cc   = idx >> 9;
    int gq = lane >> 2, tg = lane & 3;
    int n  = j * 8 + gq;
    int kb = cc * 16 + 2 * tg;

    int ks[4] = {kb, kb + 1, kb + 8, kb + 9};
    __nv_bfloat16 hi[4], lo[4];
#pragma unroll
    for (int i = 0; i < 4; i++) {
        int k = ks[i];
        float v = (k < 128) ? Wl[k * HIDDEN + n] : Wr[(k - 128) * HIDDEN + n];
        split_bf(v, hi[i], lo[i]);
    }
    wfrag[idx] = make_uint4(pack_bf2(hi[0], hi[1]), pack_bf2(hi[2], hi[3]),
                            pack_bf2(lo[0], lo[1]), pack_bf2(lo[2], lo[3]));
}

// ---------------- fused: proj (h = x @ W_op + b_op, + bf16 split) + hist + count ----------------
#define PROJ_NPB 64
__global__ __launch_bounds__(128) void proj_hist_kernel(
    const float* __restrict__ x, const float* __restrict__ W,
    const float* __restrict__ b, float* __restrict__ h,
    __nv_bfloat16* __restrict__ hh, __nv_bfloat16* __restrict__ hl,
    const int* __restrict__ dst, int* __restrict__ degi,
    const int* __restrict__ batch, float* __restrict__ cnt)
{
    __shared__ __align__(16) float xs[PROJ_NPB][N_FEAT];  // 8 KB
    int j = threadIdx.x;
    int base = blockIdx.x * PROJ_NPB;

    float w[N_FEAT];
#pragma unroll
    for (int k = 0; k < N_FEAT; k++) w[k] = W[k * HIDDEN + j];
    float bj = b[j];

    for (int i = j; i < PROJ_NPB * N_FEAT; i += 128) {
        int m = i / N_FEAT, c = i % N_FEAT;
        int node = base + m;
        xs[m][c] = (node < N_NODES) ? x[(long long)node * N_FEAT + c] : 0.f;
    }
    __syncthreads();

    int pj = (j & ~15) + perm16(j & 15);   // permuted column for bf16 side copies

    for (int m = 0; m < PROJ_NPB; m++) {
        int node = base + m;
        if (node >= N_NODES) break;
        float acc = bj;
#pragma unroll
        for (int k = 0; k < N_FEAT; k++) acc += xs[m][k] * w[k];
        long long row = (long long)node * HIDDEN;
        h[row + j] = acc;
        __nv_bfloat16 hi, lo;
        split_bf(acc, hi, lo);
        hh[row + pj] = hi;
        hl[row + pj] = lo;
    }

    // histogram + batch count (grid-stride, independent of proj output)
    int gt = blockIdx.x * 128 + threadIdx.x;
    int stride = gridDim.x * 128;
    for (int e = gt; e < N_EDGES; e += stride) atomicAdd(&degi[dst[e]], 1);
    for (int i2 = gt; i2 < N_NODES; i2 += stride) atomicAdd(&cnt[batch[i2]], 1.0f);
}

// ---------------- hierarchical scan: degi -> rowptr (exclusive) ----------------
__global__ __launch_bounds__(SCAN_T) void scan_local(
    const int* __restrict__ degi, int* __restrict__ rowptr, int* __restrict__ bsum)
{
    __shared__ int sm[SCAN_T];
    int t = threadIdx.x;
    int i = blockIdx.x * SCAN_T + t;
    int v = (i < N_NODES) ? degi[i] : 0;
    sm[t] = v;
    __syncthreads();
#pragma unroll
    for (int off = 1; off < SCAN_T; off <<= 1) {
        int add = (t >= off) ? sm[t - off] : 0;
        __syncthreads();
        sm[t] += add;
        __syncthreads();
    }
    if (i < N_NODES) rowptr[i] = sm[t] - v;
    if (t == SCAN_T - 1) bsum[blockIdx.x] = sm[t];
}

__global__ void scan_bsum(int* __restrict__ bsum) {
    if (threadIdx.x == 0) {
        int acc = 0;
        for (int b = 0; b < SCAN_NB; b++) { int v = bsum[b]; bsum[b] = acc; acc += v; }
    }
}

__global__ void scan_add(int* __restrict__ rowptr, const int* __restrict__ bsum,
                         int* __restrict__ cursor)
{
    int i = blockIdx.x * blockDim.x + threadIdx.x;
    if (i < N_NODES) {
        int v = rowptr[i] + bsum[i / SCAN_T];
        rowptr[i] = v;
        cursor[i] = v;
    }
    if (i == 0) rowptr[N_NODES] = N_EDGES;
}

// ---------------- bucket edges by dst (full parallelism) ----------------
__global__ void bucket_kernel(const int* __restrict__ src, const int* __restrict__ dst,
                              int* __restrict__ cursor, int* __restrict__ ssrc)
{
    int i = blockIdx.x * blockDim.x + threadIdx.x;
    if (i < N_EDGES) {
        int d = dst[i];
        int pos = atomicAdd(&cursor[d], 1);
        ssrc[pos] = src[i];
    }
}

// ---------------- CSR aggregate: agg[n] = mean of h[neighbors(n)] -> permuted bf16 hi/lo ----------------
__global__ __launch_bounds__(256) void aggregate_kernel(
    const int* __restrict__ rowptr, const int* __restrict__ ssrc,
    const float* __restrict__ h,
    __nv_bfloat16* __restrict__ ah, __nv_bfloat16* __restrict__ al)
{
    int node = blockIdx.x * 8 + (threadIdx.x >> 5);
    if (node >= N_NODES) return;
    int lane = threadIdx.x & 31;
    int beg = __ldg(&rowptr[node]);
    int end = __ldg(&rowptr[node + 1]);

    float4 acc = make_float4(0.f, 0.f, 0.f, 0.f);
    int e = beg;
    for (; e + 4 <= end; e += 4) {
        int s0 = __ldg(&ssrc[e + 0]);
        int s1 = __ldg(&ssrc[e + 1]);
        int s2 = __ldg(&ssrc[e + 2]);
        int s3 = __ldg(&ssrc[e + 3]);
        float4 v0 = *(const float4*)(h + (long long)s0 * HIDDEN + lane * 4);
        float4 v1 = *(const float4*)(h + (long long)s1 * HIDDEN + lane * 4);
        float4 v2 = *(const float4*)(h + (long long)s2 * HIDDEN + lane * 4);
        float4 v3 = *(const float4*)(h + (long long)s3 * HIDDEN + lane * 4);
        acc.x += (v0.x + v1.x) + (v2.x + v3.x);
        acc.y += (v0.y + v1.y) + (v2.y + v3.y);
        acc.z += (v0.z + v1.z) + (v2.z + v3.z);
        acc.w += (v0.w + v1.w) + (v2.w + v3.w);
    }
    for (; e < end; e++) {
        int s0 = __ldg(&ssrc[e]);
        float4 v0 = *(const float4*)(h + (long long)s0 * HIDDEN + lane * 4);
        acc.x += v0.x; acc.y += v0.y; acc.z += v0.z; acc.w += v0.w;
    }
    float invd = 1.0f / fmaxf((float)(end - beg), 1.0f);
    acc.x *= invd; acc.y *= invd; acc.z *= invd; acc.w *= invd;

    __nv_bfloat16 h0, l0, h1, l1, h2, l2, h3, l3;
    split_bf(acc.x, h0, l0);
    split_bf(acc.y, h1, l1);
    split_bf(acc.z, h2, l2);
    split_bf(acc.w, h3, l3);
    long long row = (long long)node * HIDDEN;
    store_perm4(ah, row, lane, h0, h1, h2, h3);
    store_perm4(al, row, lane, l0, l1, l2, l3);
}

// ---------------- tensor-core update: h = LN(elu([agg|h] @ [Wl;Wr] + bl)) ----------------
// 128 nodes x 128 cols per block, 256 threads (8 warps: 4 along M x 2 along N),
// each warp owns TWO 16-row m-tiles. Permuted A layout -> LDG.64 a-frags;
// uint4 w-frags -> LDG.128. Mainloop: 16 LDG + 48 HMMA per thread per k-chunk.
__global__ __launch_bounds__(256) void update_mma_kernel(
    const __nv_bfloat16* __restrict__ Aggh, const __nv_bfloat16* __restrict__ Aggl,
    __nv_bfloat16* __restrict__ Hh, __nv_bfloat16* __restrict__ Hl,
    float* __restrict__ h, const uint4* __restrict__ wfrag,
    const float* __restrict__ bl, const float* __restrict__ gamma,
    const float* __restrict__ beta, const int* __restrict__ batch,
    float* __restrict__ pooled, int do_pool)
{
    __shared__ float C[64][132];                  // epilogue staging, one 64-row half at a time

    int tid  = threadIdx.x;
    int lane = tid & 31;
    int w    = tid >> 5;
    int wm = w & 3, wn = w >> 2;
    int mbase = wm * 16, nbase = wn * 64;
    int base = blockIdx.x * UBM;
    int gq = lane >> 2, tg = lane & 3;

    long long rA = (long long)(base + mbase + gq) * HIDDEN;   // tile0 row 0
    long long rB = rA + 8 * HIDDEN;                           // tile0 row +8
    long long rC = rA + 64 * HIDDEN;                          // tile1 row 0
    long long rD = rA + 72 * HIDDEN;                          // tile1 row +8

    float acc[2][8][4];
#pragma unroll
    for (int t2 = 0; t2 < 2; t2++)
#pragma unroll
        for (int j = 0; j < 8; j++)
#pragma unroll
            for (int i = 0; i < 4; i++) acc[t2][j][i] = 0.f;

    // K = 256 = [agg(128) | h(128)] x [Wl; Wr], 16 chunks of 16
#pragma unroll 2
    for (int cc = 0; cc < 16; cc++) {
        const __nv_bfloat16* PH = (cc < 8) ? Aggh : Hh;
        const __nv_bfloat16* PL = (cc < 8) ? Aggl : Hl;
        int koff = (cc & 7) * 16 + 4 * tg;    // permuted: holds {2tg,2tg+1,2tg+8,2tg+9}

        unsigned a0h[4], a0l[4], a1h[4], a1l[4];
        uint2 t;
        t = *(const uint2*)(PH + rA + koff); a0h[0] = t.x; a0h[2] = t.y;
        t = *(const uint2*)(PH + rB + koff); a0h[1] = t.x; a0h[3] = t.y;
        t = *(const uint2*)(PL + rA + koff); a0l[0] = t.x; a0l[2] = t.y;
        t = *(const uint2*)(PL + rB + koff); a0l[1] = t.x; a0l[3] = t.y;
        t = *(const uint2*)(PH + rC + koff); a1h[0] = t.x; a1h[2] = t.y;
        t = *(const uint2*)(PH + rD + koff); a1h[1] = t.x; a1h[3] = t.y;
        t = *(const uint2*)(PL + rC + koff); a1l[0] = t.x; a1l[2] = t.y;
        t = *(const uint2*)(PL + rD + koff); a1l[1] = t.x; a1l[3] = t.y;

        const uint4* wf = wfrag + (long long)(cc * 16 + wn * 8) * 32 + lane;
#pragma unroll
        for (int jj = 0; jj < 8; jj++) {
            uint4 b = __ldg(wf + jj * 32);
            mma16816(acc[0][jj], a0h, b.x, b.y);
            mma16816(acc[0][jj], a0h, b.z, b.w);
            mma16816(acc[0][jj], a0l, b.x, b.y);
            mma16816(acc[1][jj], a1h, b.x, b.y);
            mma16816(acc[1][jj], a1h, b.z, b.w);
            mma16816(acc[1][jj], a1l, b.x, b.y);
        }
    }

    // ---- epilogue in two 64-row halves through smem ----
    float4 bia = *(const float4*)(bl + lane * 4);
    float4 gm  = *(const float4*)(gamma + lane * 4);
    float4 bt  = *(const float4*)(beta + lane * 4);

    for (int half = 0; half < 2; half++) {
        __syncthreads();   // C free (or initial)
#pragma unroll
        for (int j = 0; j < 8; j++) {
            int c = nbase + j * 8 + 2 * tg;
            int r0 = mbase + gq;
            C[r0][c]     = acc[half][j][0];
            C[r0][c + 1] = acc[half][j][1];
            C[r0 + 8][c]     = acc[half][j][2];
            C[r0 + 8][c + 1] = acc[half][j][3];
        }
        __syncthreads();

        // warp w handles rows w*8..w*8+7 of this half
        for (int rr = 0; rr < 8; rr++) {
            int row = w * 8 + rr;
            int node = base + half * 64 + row;
            if (node >= N_NODES) continue;
            float4 v = *(float4*)&C[row][lane * 4];
            v.x += bia.x; v.y += bia.y; v.z += bia.z; v.w += bia.w;
            v.x = (v.x > 0.f) ? v.x : expm1f(v.x);
            v.y = (v.y > 0.f) ? v.y : expm1f(v.y);
            v.z = (v.z > 0.f) ? v.z : expm1f(v.z);
            v.w = (v.w > 0.f) ? v.w : expm1f(v.w);
            float s = v.x + v.y + v.z + v.w;
            float q = v.x * v.x + v.y * v.y + v.z * v.z + v.w * v.w;
#pragma unroll
            for (int o = 16; o > 0; o >>= 1) {
                s += __shfl_xor_sync(0xffffffffu, s, o);
                q += __shfl_xor_sync(0xffffffffu, q, o);
            }
            const float invH = 1.0f / HIDDEN;
            float mu = s * invH;
            float var = fmaxf(q * invH - mu * mu, 0.f);
            float rstd = rsqrtf(var + 1e-5f);
            float4 o4;
            o4.x = (v.x - mu) * rstd * gm.x + bt.x;
            o4.y = (v.y - mu) * rstd * gm.y + bt.y;
            o4.z = (v.z - mu) * rstd * gm.z + bt.z;
            o4.w = (v.w - mu) * rstd * gm.w + bt.w;
            long long rofs = (long long)node * HIDDEN;
            *(float4*)(h + rofs + lane * 4) = o4;
            __nv_bfloat16 h0, l0, h1, l1, h2, l2, h3, l3;
            split_bf(o4.x, h0, l0);
            split_bf(o4.y, h1, l1);
            split_bf(o4.z, h2, l2);
            split_bf(o4.w, h3, l3);
            store_perm4(Hh, rofs, lane, h0, h1, h2, h3);
            store_perm4(Hl, rofs, lane, l0, l1, l2, l3);
            if (do_pool) {
                int g = __ldg(&batch[node]);
                red_add_v4(pooled + (long long)g * HIDDEN + lane * 4, o4);
            }
        }
    }
}

// ---------------- head: pooled mean + two GEMVs ----------------
__global__ void head_kernel(const float* __restrict__ pooled, const float* __restrict__ cnt,
                            const float* __restrict__ Wm, const float* __restrict__ bm,
                            const float* __restrict__ Wt, const float* __restrict__ bt,
                            float* __restrict__ out)
{
    int g = blockIdx.x * blockDim.x + threadIdx.x;
    if (g >= N_GRAPHS) return;
    float inv = 1.0f / fmaxf(cnt[g], 1.0f);
    float s1 = 0.f, s2 = 0.f;
#pragma unroll 4
    for (int j = 0; j < HIDDEN; j++) {
        float p = pooled[g * HIDDEN + j];
        s1 += p * Wm[j];
        s2 += p * Wt[j];
    }
    out[g] = s1 * inv + bm[0];
    out[N_GRAPHS + g] = s2 * inv + bt[0];
}

// ---------------- launch ----------------
extern "C" void kernel_launch(void* const* d_in, const int* in_sizes, int n_in,
                              void* d_out, int out_size)
{
    const float* x      = (const float*)d_in[0];
    const int*   edge   = (const int*)d_in[1];
    const int*   batch  = (const int*)d_in[2];
    const float* W_op   = (const float*)d_in[3];
    const float* b_op   = (const float*)d_in[4];
    const float* W_l    = (const float*)d_in[5];
    const float* b_l    = (const float*)d_in[6];
    const float* W_r    = (const float*)d_in[7];
    const float* gamma  = (const float*)d_in[8];
    const float* beta   = (const float*)d_in[9];
    const float* W_mem  = (const float*)d_in[10];
    const float* b_mem  = (const float*)d_in[11];
    const float* W_time = (const float*)d_in[12];
    const float* b_time = (const float*)d_in[13];
    float* out = (float*)d_out;

    const int* src = edge;
    const int* dst = edge + N_EDGES;

    float *p_h, *p_cnt, *p_pool;
    __nv_bfloat16 *p_hh, *p_hl, *p_ah, *p_al;
    uint4 *p_wfrag;
    int *p_degi, *p_rowptr, *p_cursor, *p_ssrc, *p_bsum;
    cudaGetSymbolAddress((void**)&p_h, g_h);
    cudaGetSymbolAddress((void**)&p_hh, g_hh);
    cudaGetSymbolAddress((void**)&p_hl, g_hl);
    cudaGetSymbolAddress((void**)&p_ah, g_ah);
    cudaGetSymbolAddress((void**)&p_al, g_al);
    cudaGetSymbolAddress((void**)&p_wfrag, g_wfrag);
    cudaGetSymbolAddress((void**)&p_cnt, g_cnt);
    cudaGetSymbolAddress((void**)&p_pool, g_pool);
    cudaGetSymbolAddress((void**)&p_degi, g_degi);
    cudaGetSymbolAddress((void**)&p_rowptr, g_rowptr);
    cudaGetSymbolAddress((void**)&p_cursor, g_cursor);
    cudaGetSymbolAddress((void**)&p_ssrc, g_ssrc);
    cudaGetSymbolAddress((void**)&p_bsum, g_bsum);

    // 1: zero accumulated state
    zero_kernel<<<256, 256>>>(p_degi, p_cnt, p_pool);

    // 2: pre-split weights into uint4 b-fragment records (once per launch)
    wsplit_kernel<<<32, 256>>>(W_l, W_r, p_wfrag);

    // 3: input projection (+ permuted bf16 split) + degree histogram + batch count
    proj_hist_kernel<<<(N_NODES + PROJ_NPB - 1) / PROJ_NPB, 128>>>(
        x, W_op, b_op, p_h, p_hh, p_hl, dst, p_degi, batch, p_cnt);

    // 4-6: hierarchical scan (no spins)
    scan_local<<<SCAN_NB, SCAN_T>>>(p_degi, p_rowptr, p_bsum);
    scan_bsum<<<1, 32>>>(p_bsum);
    scan_add<<<(N_NODES + 255) / 256, 256>>>(p_rowptr, p_bsum, p_cursor);

    // 7: bucket edges at full parallelism
    bucket_kernel<<<(N_EDGES + 255) / 256, 256>>>(src, dst, p_cursor, p_ssrc);

    // 8..11: two layers of aggregate + tensor-core update
    for (int layer = 0; layer < 2; layer++) {
        aggregate_kernel<<<(N_NODES + 7) / 8, 256>>>(p_rowptr, p_ssrc, p_h, p_ah, p_al);
        update_mma_kernel<<<(N_NODES + UBM - 1) / UBM, 256>>>(
            p_ah, p_al, p_hh, p_hl, p_h, p_wfrag,
            b_l, gamma, beta, batch, p_pool, layer == 1);
    }

    // 12: head
    head_kernel<<<1, 256>>>(p_pool, p_cnt, W_mem, b_mem, W_time, b_time, out);
}

// round 12
// speedup vs baseline: 1.2690x; 1.2690x over previous
#include <cuda_runtime.h>
#include <cuda_bf16.h>

#define N_NODES  100000
#define N_EDGES  1600000
#define N_FEAT   32
#define HIDDEN   128
#define N_GRAPHS 256

#define SCAN_T   1024
#define SCAN_NB  98          // ceil(100000/1024)

#define UBM 128              // update kernel M-tile (nodes per block)
#define NPAD (N_NODES + UBM) // zero-padded rows for tail block

// ---------------- scratch (static device globals; no allocation) ----------------
__device__ float         g_h [NPAD * HIDDEN];   // fp32 h, natural layout (aggregate gathers this)
__device__ __nv_bfloat16 g_hh[NPAD * HIDDEN];   // h hi (bf16)
__device__ __nv_bfloat16 g_hl[NPAD * HIDDEN];   // h lo (bf16)
__device__ __nv_bfloat16 g_ah[NPAD * HIDDEN];   // agg hi
__device__ __nv_bfloat16 g_al[NPAD * HIDDEN];   // agg lo
__device__ uint2 g_wfrag[16 * 16 * 2 * 32];     // [cc][j][hi/lo][lane] b-fragments, 128KB
__device__ int   g_degi[N_NODES];
__device__ int   g_rowptr[N_NODES + 1];
__device__ int   g_cursor[N_NODES];
__device__ int   g_ssrc[N_EDGES];               // 6.4 MB
__device__ int   g_bsum[SCAN_NB];
__device__ float g_cnt[N_GRAPHS];
__device__ float g_pool[N_GRAPHS * HIDDEN];

// ---------------- helpers ----------------
__device__ __forceinline__ void red_add_v4(float* addr, float4 v) {
    asm volatile("red.global.add.v4.f32 [%0], {%1, %2, %3, %4};"
                 :: "l"(addr), "f"(v.x), "f"(v.y), "f"(v.z), "f"(v.w)
                 : "memory");
}

__device__ __forceinline__ unsigned pack_bf2(__nv_bfloat16 a, __nv_bfloat16 b) {
    __nv_bfloat162 t;
    t.x = a; t.y = b;
    return *reinterpret_cast<unsigned*>(&t);
}

__device__ __forceinline__ void split_bf(float v, __nv_bfloat16& hi, __nv_bfloat16& lo) {
    hi = __float2bfloat16(v);
    lo = __float2bfloat16(v - __bfloat162float(hi));
}

__device__ __forceinline__ void mma16816(float* d, const unsigned* a, unsigned b0, unsigned b1) {
    asm volatile(
        "mma.sync.aligned.m16n8k16.row.col.f32.bf16.bf16.f32 "
        "{%0,%1,%2,%3}, {%4,%5,%6,%7}, {%8,%9}, {%0,%1,%2,%3};\n"
        : "+f"(d[0]), "+f"(d[1]), "+f"(d[2]), "+f"(d[3])
        : "r"(a[0]), "r"(a[1]), "r"(a[2]), "r"(a[3]), "r"(b0), "r"(b1));
}

// ---------------- zero: degi, cnt, pool ----------------
__global__ void zero_kernel(int* __restrict__ degi, float* __restrict__ cnt,
                            float* __restrict__ pool)
{
    int i = blockIdx.x * blockDim.x + threadIdx.x;
    int stride = gridDim.x * blockDim.x;
    for (int j = i; j < N_NODES; j += stride) degi[j] = 0;
    for (int j = i; j < N_GRAPHS * HIDDEN; j += stride) pool[j] = 0.f;
    if (i < N_GRAPHS) cnt[i] = 0.f;
}

// ---------------- weight pre-split into b-fragment layout ----------------
__global__ void wsplit_kernel(const float* __restrict__ Wl, const float* __restrict__ Wr,
                              uint2* __restrict__ wfrag)
{
    int idx = blockIdx.x * 256 + threadIdx.x;      // 0..16383
    int lane = idx & 31;
    int p    = (idx >> 5) & 1;
    int j    = (idx >> 6) & 15;
    int cc   = idx >> 10;
    int gq = lane >> 2, tg = lane & 3;
    int n  = j * 8 + gq;
    int kb = cc * 16 + 2 * tg;

    int ks[4] = {kb, kb + 1, kb + 8, kb + 9};
    __nv_bfloat16 b[4];
#pragma unroll
    for (int i = 0; i < 4; i++) {
        int k = ks[i];
        float v = (k < 128) ? Wl[k * HIDDEN + n] : Wr[(k - 128) * HIDDEN + n];
        __nv_bfloat16 hi, lo;
        split_bf(v, hi, lo);
        b[i] = p ? lo : hi;
    }
    wfrag[idx] = make_uint2(pack_bf2(b[0], b[1]), pack_bf2(b[2], b[3]));
}

// ---------------- fused: proj (h = x @ W_op + b_op, + bf16 split) + hist + count ----------------
#define PROJ_NPB 64
__global__ __launch_bounds__(128) void proj_hist_kernel(
    const float* __restrict__ x, const float* __restrict__ W,
    const float* __restrict__ b, float* __restrict__ h,
    __nv_bfloat16* __restrict__ hh, __nv_bfloat16* __restrict__ hl,
    const int* __restrict__ dst, int* __restrict__ degi,
    const int* __restrict__ batch, float* __restrict__ cnt)
{
    __shared__ __align__(16) float xs[PROJ_NPB][N_FEAT];  // 8 KB
    int j = threadIdx.x;
    int base = blockIdx.x * PROJ_NPB;

    float w[N_FEAT];
#pragma unroll
    for (int k = 0; k < N_FEAT; k++) w[k] = W[k * HIDDEN + j];
    float bj = b[j];

    for (int i = j; i < PROJ_NPB * N_FEAT; i += 128) {
        int m = i / N_FEAT, c = i % N_FEAT;
        int node = base + m;
        xs[m][c] = (node < N_NODES) ? x[(long long)node * N_FEAT + c] : 0.f;
    }
    __syncthreads();

    for (int m = 0; m < PROJ_NPB; m++) {
        int node = base + m;
        if (node >= N_NODES) break;
        float acc = bj;
#pragma unroll
        for (int k = 0; k < N_FEAT; k++) acc += xs[m][k] * w[k];
        long long ofs = (long long)node * HIDDEN + j;
        h[ofs] = acc;
        __nv_bfloat16 hi, lo;
        split_bf(acc, hi, lo);
        hh[ofs] = hi;
        hl[ofs] = lo;
    }

    // histogram + batch count (grid-stride, independent of proj output)
    int gt = blockIdx.x * 128 + threadIdx.x;
    int stride = gridDim.x * 128;
    for (int e = gt; e < N_EDGES; e += stride) atomicAdd(&degi[dst[e]], 1);
    for (int i2 = gt; i2 < N_NODES; i2 += stride) atomicAdd(&cnt[batch[i2]], 1.0f);
}

// ---------------- hierarchical scan: degi -> rowptr (exclusive) ----------------
__global__ __launch_bounds__(SCAN_T) void scan_local(
    const int* __restrict__ degi, int* __restrict__ rowptr, int* __restrict__ bsum)
{
    __shared__ int sm[SCAN_T];
    int t = threadIdx.x;
    int i = blockIdx.x * SCAN_T + t;
    int v = (i < N_NODES) ? degi[i] : 0;
    sm[t] = v;
    __syncthreads();
#pragma unroll
    for (int off = 1; off < SCAN_T; off <<= 1) {
        int add = (t >= off) ? sm[t - off] : 0;
        __syncthreads();
        sm[t] += add;
        __syncthreads();
    }
    if (i < N_NODES) rowptr[i] = sm[t] - v;
    if (t == SCAN_T - 1) bsum[blockIdx.x] = sm[t];
}

__global__ void scan_bsum(int* __restrict__ bsum) {
    if (threadIdx.x == 0) {
        int acc = 0;
        for (int b = 0; b < SCAN_NB; b++) { int v = bsum[b]; bsum[b] = acc; acc += v; }
    }
}

__global__ void scan_add(int* __restrict__ rowptr, const int* __restrict__ bsum,
                         int* __restrict__ cursor)
{
    int i = blockIdx.x * blockDim.x + threadIdx.x;
    if (i < N_NODES) {
        int v = rowptr[i] + bsum[i / SCAN_T];
        rowptr[i] = v;
        cursor[i] = v;
    }
    if (i == 0) rowptr[N_NODES] = N_EDGES;
}

// ---------------- bucket edges by dst (full parallelism) ----------------
__global__ void bucket_kernel(const int* __restrict__ src, const int* __restrict__ dst,
                              int* __restrict__ cursor, int* __restrict__ ssrc)
{
    int i = blockIdx.x * blockDim.x + threadIdx.x;
    if (i < N_EDGES) {
        int d = dst[i];
        int pos = atomicAdd(&cursor[d], 1);
        ssrc[pos] = src[i];
    }
}

// ---------------- CSR aggregate: agg[n] = mean of h[neighbors(n)] -> bf16 hi/lo ----------------
__global__ __launch_bounds__(256) void aggregate_kernel(
    const int* __restrict__ rowptr, const int* __restrict__ ssrc,
    const float* __restrict__ h,
    __nv_bfloat16* __restrict__ ah, __nv_bfloat16* __restrict__ al)
{
    int node = blockIdx.x * 8 + (threadIdx.x >> 5);
    if (node >= N_NODES) return;
    int lane = threadIdx.x & 31;
    int beg = __ldg(&rowptr[node]);
    int end = __ldg(&rowptr[node + 1]);

    float4 acc = make_float4(0.f, 0.f, 0.f, 0.f);
    int e = beg;
    for (; e + 4 <= end; e += 4) {
        int s0 = __ldg(&ssrc[e + 0]);
        int s1 = __ldg(&ssrc[e + 1]);
        int s2 = __ldg(&ssrc[e + 2]);
        int s3 = __ldg(&ssrc[e + 3]);
        float4 v0 = *(const float4*)(h + (long long)s0 * HIDDEN + lane * 4);
        float4 v1 = *(const float4*)(h + (long long)s1 * HIDDEN + lane * 4);
        float4 v2 = *(const float4*)(h + (long long)s2 * HIDDEN + lane * 4);
        float4 v3 = *(const float4*)(h + (long long)s3 * HIDDEN + lane * 4);
        acc.x += (v0.x + v1.x) + (v2.x + v3.x);
        acc.y += (v0.y + v1.y) + (v2.y + v3.y);
        acc.z += (v0.z + v1.z) + (v2.z + v3.z);
        acc.w += (v0.w + v1.w) + (v2.w + v3.w);
    }
    for (; e < end; e++) {
        int s0 = __ldg(&ssrc[e]);
        float4 v0 = *(const float4*)(h + (long long)s0 * HIDDEN + lane * 4);
        acc.x += v0.x; acc.y += v0.y; acc.z += v0.z; acc.w += v0.w;
    }
    float invd = 1.0f / fmaxf((float)(end - beg), 1.0f);
    acc.x *= invd; acc.y *= invd; acc.z *= invd; acc.w *= invd;

    __nv_bfloat16 h0, l0, h1, l1, h2, l2, h3, l3;
    split_bf(acc.x, h0, l0);
    split_bf(acc.y, h1, l1);
    split_bf(acc.z, h2, l2);
    split_bf(acc.w, h3, l3);
    long long ofs = (long long)node * HIDDEN + lane * 4;
    *(uint2*)(ah + ofs) = make_uint2(pack_bf2(h0, h1), pack_bf2(h2, h3));
    *(uint2*)(al + ofs) = make_uint2(pack_bf2(l0, l1), pack_bf2(l2, l3));
}

// ---------------- tensor-core update: h = LN(elu([agg|h] @ [Wl;Wr] + bl)) ----------------
// 128 nodes x 128 cols per block, 256 threads (8 warps: 4 along M x 2 along N),
// each warp owns TWO 16-row m-tiles. __launch_bounds__(256,2) forces <=128 regs
// so 2 blocks/SM (4 warps/SMSP) hide the per-chunk L2 latency.
__global__ __launch_bounds__(256, 2) void update_mma_kernel(
    const __nv_bfloat16* __restrict__ Aggh, const __nv_bfloat16* __restrict__ Aggl,
    __nv_bfloat16* __restrict__ Hh, __nv_bfloat16* __restrict__ Hl,
    float* __restrict__ h, const uint2* __restrict__ wfrag,
    const float* __restrict__ bl, const float* __restrict__ gamma,
    const float* __restrict__ beta, const int* __restrict__ batch,
    float* __restrict__ pooled, int do_pool)
{
    __shared__ float C[64][132];                  // epilogue staging, one 64-row half at a time

    int tid  = threadIdx.x;
    int lane = tid & 31;
    int w    = tid >> 5;
    int wm = w & 3, wn = w >> 2;
    int mbase = wm * 16, nbase = wn * 64;
    int base = blockIdx.x * UBM;
    int gq = lane >> 2, tg = lane & 3;

    // 32-bit offsets (arrays are < 2^31 elements) to save registers
    unsigned rA = (unsigned)(base + mbase + gq) * HIDDEN;   // tile0 row 0
    unsigned rB = rA + 8 * HIDDEN;                          // tile0 row +8
    unsigned rC = rA + 64 * HIDDEN;                         // tile1 row 0
    unsigned rD = rA + 72 * HIDDEN;                         // tile1 row +8

    float acc[2][8][4];
#pragma unroll
    for (int t2 = 0; t2 < 2; t2++)
#pragma unroll
        for (int j = 0; j < 8; j++)
#pragma unroll
            for (int i = 0; i < 4; i++) acc[t2][j][i] = 0.f;

    // K = 256 = [agg(128) | h(128)] x [Wl; Wr], 16 chunks of 16
#pragma unroll 1
    for (int cc = 0; cc < 16; cc++) {
        const __nv_bfloat16* PH = (cc < 8) ? Aggh : Hh;
        const __nv_bfloat16* PL = (cc < 8) ? Aggl : Hl;
        unsigned kk = (cc & 7) * 16 + 2 * tg;

        // batch all loads (a-frags + w-frags) so they issue back-to-back
        unsigned a0h[4], a0l[4], a1h[4], a1l[4];
        a0h[0] = *(const unsigned*)(PH + rA + kk);
        a0h[1] = *(const unsigned*)(PH + rB + kk);
        a0h[2] = *(const unsigned*)(PH + rA + kk + 8);
        a0h[3] = *(const unsigned*)(PH + rB + kk + 8);
        a1h[0] = *(const unsigned*)(PH + rC + kk);
        a1h[1] = *(const unsigned*)(PH + rD + kk);
        a1h[2] = *(const unsigned*)(PH + rC + kk + 8);
        a1h[3] = *(const unsigned*)(PH + rD + kk + 8);
        a0l[0] = *(const unsigned*)(PL + rA + kk);
        a0l[1] = *(const unsigned*)(PL + rB + kk);
        a0l[2] = *(const unsigned*)(PL + rA + kk + 8);
        a0l[3] = *(const unsigned*)(PL + rB + kk + 8);
        a1l[0] = *(const unsigned*)(PL + rC + kk);
        a1l[1] = *(const unsigned*)(PL + rD + kk);
        a1l[2] = *(const unsigned*)(PL + rC + kk + 8);
        a1l[3] = *(const unsigned*)(PL + rD + kk + 8);

        const uint2* wf = wfrag + (cc * 16 + wn * 8) * 2 * 32 + lane;
        uint2 wreg[16];
#pragma unroll
        for (int jj = 0; jj < 8; jj++) {
            wreg[2 * jj]     = __ldg(wf + (jj * 2) * 32);
            wreg[2 * jj + 1] = __ldg(wf + (jj * 2 + 1) * 32);
        }

#pragma unroll
        for (int jj = 0; jj < 8; jj++) {
            uint2 bh = wreg[2 * jj];
            uint2 bb = wreg[2 * jj + 1];
            mma16816(acc[0][jj], a0h, bh.x, bh.y);
            mma16816(acc[0][jj], a0h, bb.x, bb.y);
            mma16816(acc[0][jj], a0l, bh.x, bh.y);
            mma16816(acc[1][jj], a1h, bh.x, bh.y);
            mma16816(acc[1][jj], a1h, bb.x, bb.y);
            mma16816(acc[1][jj], a1l, bh.x, bh.y);
        }
    }

    // ---- epilogue in two 64-row halves through smem ----
    float4 bia = *(const float4*)(bl + lane * 4);
    float4 gm  = *(const float4*)(gamma + lane * 4);
    float4 bt  = *(const float4*)(beta + lane * 4);

    for (int half = 0; half < 2; half++) {
        __syncthreads();   // C free (or initial)
#pragma unroll
        for (int j = 0; j < 8; j++) {
            int c = nbase + j * 8 + 2 * tg;
            int r0 = mbase + gq;
            C[r0][c]     = acc[half][j][0];
            C[r0][c + 1] = acc[half][j][1];
            C[r0 + 8][c]     = acc[half][j][2];
            C[r0 + 8][c + 1] = acc[half][j][3];
        }
        __syncthreads();

        // warp w handles rows w*8..w*8+7 of this half
        for (int rr = 0; rr < 8; rr++) {
            int row = w * 8 + rr;
            int node = base + half * 64 + row;
            if (node >= N_NODES) continue;
            float4 v = *(float4*)&C[row][lane * 4];
            v.x += bia.x; v.y += bia.y; v.z += bia.z; v.w += bia.w;
            v.x = (v.x > 0.f) ? v.x : expm1f(v.x);
            v.y = (v.y > 0.f) ? v.y : expm1f(v.y);
            v.z = (v.z > 0.f) ? v.z : expm1f(v.z);
            v.w = (v.w > 0.f) ? v.w : expm1f(v.w);
            float s = v.x + v.y + v.z + v.w;
            float q = v.x * v.x + v.y * v.y + v.z * v.z + v.w * v.w;
#pragma unroll
            for (int o = 16; o > 0; o >>= 1) {
                s += __shfl_xor_sync(0xffffffffu, s, o);
                q += __shfl_xor_sync(0xffffffffu, q, o);
            }
            const float invH = 1.0f / HIDDEN;
            float mu = s * invH;
            float var = fmaxf(q * invH - mu * mu, 0.f);
            float rstd = rsqrtf(var + 1e-5f);
            float4 o4;
            o4.x = (v.x - mu) * rstd * gm.x + bt.x;
            o4.y = (v.y - mu) * rstd * gm.y + bt.y;
            o4.z = (v.z - mu) * rstd * gm.z + bt.z;
            o4.w = (v.w - mu) * rstd * gm.w + bt.w;
            long long ofs = (long long)node * HIDDEN + lane * 4;
            *(float4*)(h + ofs) = o4;
            __nv_bfloat16 h0, l0, h1, l1, h2, l2, h3, l3;
            split_bf(o4.x, h0, l0);
            split_bf(o4.y, h1, l1);
            split_bf(o4.z, h2, l2);
            split_bf(o4.w, h3, l3);
            *(uint2*)(Hh + ofs) = make_uint2(pack_bf2(h0, h1), pack_bf2(h2, h3));
            *(uint2*)(Hl + ofs) = make_uint2(pack_bf2(l0, l1), pack_bf2(l2, l3));
            if (do_pool) {
                int g = __ldg(&batch[node]);
                red_add_v4(pooled + (long long)g * HIDDEN + lane * 4, o4);
            }
        }
    }
}

// ---------------- head: pooled mean + two GEMVs ----------------
__global__ void head_kernel(const float* __restrict__ pooled, const float* __restrict__ cnt,
                            const float* __restrict__ Wm, const float* __restrict__ bm,
                            const float* __restrict__ Wt, const float* __restrict__ bt,
                            float* __restrict__ out)
{
    int g = blockIdx.x * blockDim.x + threadIdx.x;
    if (g >= N_GRAPHS) return;
    float inv = 1.0f / fmaxf(cnt[g], 1.0f);
    float s1 = 0.f, s2 = 0.f;
#pragma unroll 4
    for (int j = 0; j < HIDDEN; j++) {
        float p = pooled[g * HIDDEN + j];
        s1 += p * Wm[j];
        s2 += p * Wt[j];
    }
    out[g] = s1 * inv + bm[0];
    out[N_GRAPHS + g] = s2 * inv + bt[0];
}

// ---------------- launch ----------------
extern "C" void kernel_launch(void* const* d_in, const int* in_sizes, int n_in,
                              void* d_out, int out_size)
{
    const float* x      = (const float*)d_in[0];
    const int*   edge   = (const int*)d_in[1];
    const int*   batch  = (const int*)d_in[2];
    const float* W_op   = (const float*)d_in[3];
    const float* b_op   = (const float*)d_in[4];
    const float* W_l    = (const float*)d_in[5];
    const float* b_l    = (const float*)d_in[6];
    const float* W_r    = (const float*)d_in[7];
    const float* gamma  = (const float*)d_in[8];
    const float* beta   = (const float*)d_in[9];
    const float* W_mem  = (const float*)d_in[10];
    const float* b_mem  = (const float*)d_in[11];
    const float* W_time = (const float*)d_in[12];
    const float* b_time = (const float*)d_in[13];
    float* out = (float*)d_out;

    const int* src = edge;
    const int* dst = edge + N_EDGES;

    float *p_h, *p_cnt, *p_pool;
    __nv_bfloat16 *p_hh, *p_hl, *p_ah, *p_al;
    uint2 *p_wfrag;
    int *p_degi, *p_rowptr, *p_cursor, *p_ssrc, *p_bsum;
    cudaGetSymbolAddress((void**)&p_h, g_h);
    cudaGetSymbolAddress((void**)&p_hh, g_hh);
    cudaGetSymbolAddress((void**)&p_hl, g_hl);
    cudaGetSymbolAddress((void**)&p_ah, g_ah);
    cudaGetSymbolAddress((void**)&p_al, g_al);
    cudaGetSymbolAddress((void**)&p_wfrag, g_wfrag);
    cudaGetSymbolAddress((void**)&p_cnt, g_cnt);
    cudaGetSymbolAddress((void**)&p_pool, g_pool);
    cudaGetSymbolAddress((void**)&p_degi, g_degi);
    cudaGetSymbolAddress((void**)&p_rowptr, g_rowptr);
    cudaGetSymbolAddress((void**)&p_cursor, g_cursor);
    cudaGetSymbolAddress((void**)&p_ssrc, g_ssrc);
    cudaGetSymbolAddress((void**)&p_bsum, g_bsum);

    // 1: zero accumulated state
    zero_kernel<<<256, 256>>>(p_degi, p_cnt, p_pool);

    // 2: pre-split weights into b-fragment layout (once per launch)
    wsplit_kernel<<<64, 256>>>(W_l, W_r, p_wfrag);

    // 3: input projection (+ bf16 split) + degree histogram + batch count
    proj_hist_kernel<<<(N_NODES + PROJ_NPB - 1) / PROJ_NPB, 128>>>(
        x, W_op, b_op, p_h, p_hh, p_hl, dst, p_degi, batch, p_cnt);

    // 4-6: hierarchical scan (no spins)
    scan_local<<<SCAN_NB, SCAN_T>>>(p_degi, p_rowptr, p_bsum);
    scan_bsum<<<1, 32>>>(p_bsum);
    scan_add<<<(N_NODES + 255) / 256, 256>>>(p_rowptr, p_bsum, p_cursor);

    // 7: bucket edges at full parallelism
    bucket_kernel<<<(N_EDGES + 255) / 256, 256>>>(src, dst, p_cursor, p_ssrc);

    // 8..11: two layers of aggregate + tensor-core update
    for (int layer = 0; layer < 2; layer++) {
        aggregate_kernel<<<(N_NODES + 7) / 8, 256>>>(p_rowptr, p_ssrc, p_h, p_ah, p_al);
        update_mma_kernel<<<(N_NODES + UBM - 1) / UBM, 256>>>(
            p_ah, p_al, p_hh, p_hl, p_h, p_wfrag,
            b_l, gamma, beta, batch, p_pool, layer == 1);
    }

    // 12: head
    head_kernel<<<1, 256>>>(p_pool, p_cnt, W_mem, b_mem, W_time, b_time, out);
}